// round 12
// baseline (speedup 1.0000x reference)
#include <cuda_runtime.h>
#include <cuda_fp16.h>
#include <math.h>
#include <stdint.h>

// Shapes (fixed): x[64,512,512] f32, k*[512,1024] f32, out[64,512,1024] f32
#define Bsz 64
#define Tsz 512
#define Dsz 512
#define Hsz 1024
#define Msz (Bsz * Tsz)   // 32768
#define Kd  512
#define Nc  3072          // fused N = 3*H: cols [z | r | h] grouped per projection

// ---------------- device scratch (static, no runtime alloc) ----------------
// g_P[m][col]: col = proj*1024 + n  -> row = [z(0:1024) | r(1024:2048) | h(2048:3072)]
__device__ __align__(16) __half g_P[(size_t)Msz * Nc];        // 192 MB
__device__ __align__(16) __half g_A[(size_t)Msz * Kd];        // 32 MB
__device__ __align__(16) __half g_B[(size_t)Nc * Kd];         // 3 MB

// ---------------- PTX helpers (base-sm_103 features only) ----------------
__device__ __forceinline__ uint32_t smem_u32(const void* p) {
    uint32_t a;
    asm("{ .reg .u64 t; cvta.to.shared.u64 t, %1; cvt.u32.u64 %0, t; }" : "=r"(a) : "l"(p));
    return a;
}
__device__ __forceinline__ void cpasync16(uint32_t dst, const void* src) {
    asm volatile("cp.async.cg.shared.global [%0], [%1], 16;" :: "r"(dst), "l"(src) : "memory");
}
__device__ __forceinline__ void cp_commit() {
    asm volatile("cp.async.commit_group;" ::: "memory");
}
template <int N>
__device__ __forceinline__ void cp_wait() {
    asm volatile("cp.async.wait_group %0;" :: "n"(N) : "memory");
}
__device__ __forceinline__ void ldsm_x4(uint32_t& d0, uint32_t& d1, uint32_t& d2,
                                        uint32_t& d3, uint32_t addr) {
    asm volatile("ldmatrix.sync.aligned.m8n8.x4.shared.b16 {%0,%1,%2,%3}, [%4];"
                 : "=r"(d0), "=r"(d1), "=r"(d2), "=r"(d3) : "r"(addr));
}
__device__ __forceinline__ void mma16816(float& c0, float& c1, float& c2, float& c3,
                                         uint32_t a0, uint32_t a1, uint32_t a2, uint32_t a3,
                                         uint32_t b0, uint32_t b1) {
    asm volatile(
        "mma.sync.aligned.m16n8k16.row.col.f32.f16.f16.f32 "
        "{%0,%1,%2,%3}, {%4,%5,%6,%7}, {%8,%9}, {%0,%1,%2,%3};"
        : "+f"(c0), "+f"(c1), "+f"(c2), "+f"(c3)
        : "r"(a0), "r"(a1), "r"(a2), "r"(a3), "r"(b0), "r"(b1));
}

// ---------------- conversion kernels ----------------
__global__ __launch_bounds__(256) void convA_kernel(const float* __restrict__ x) {
    int idx = blockIdx.x * blockDim.x + threadIdx.x;       // Msz*128 threads
    int m  = idx >> 7;
    int kg = (idx & 127) << 2;
    float4 v = *(const float4*)(x + (size_t)m * Dsz + kg);
    __half h[4] = {__float2half(v.x), __float2half(v.y),
                   __float2half(v.z), __float2half(v.w)};
    uint64_t hp;
    memcpy(&hp, h, 8);
    *(uint64_t*)(g_A + (size_t)m * Kd + kg) = hp;
}

// B[col][k] = fp16(W_p[k][n]) with col = proj*1024 + n
__global__ __launch_bounds__(256) void convB_kernel(const float* __restrict__ kz,
                                                    const float* __restrict__ kr,
                                                    const float* __restrict__ kh) {
    int idx = blockIdx.x * blockDim.x + threadIdx.x;       // 3*1024*64 threads
    int proj = idx >> 16;
    int r    = idx & 65535;
    int n  = r >> 6;
    int kg = (r & 63) << 3;
    const float* W = (proj == 0) ? kz : (proj == 1) ? kr : kh;
    const int col = proj * Hsz + n;

    __half h[8];
#pragma unroll
    for (int j = 0; j < 8; j++)
        h[j] = __float2half(W[(size_t)(kg + j) * Hsz + n]);
    uint4 hp;
    memcpy(&hp, h, 16);
    *(uint4*)(g_B + (size_t)col * Kd + kg) = hp;
}

// ---------------- fused mma.sync GEMM (M=32768, N=3072, K=512) ----------------
// BM=128, BN=128, BK=64. 256 threads = 8 warps (2m x 4n), warp tile 64x32.
// 3-stage cp.async pipeline (96KB), 2 CTAs/SM, fp16 epilogue.
#define BKc 64
#define STAGES 3
#define NK (Kd / BKc)                   // 8
#define A_STG 16384
#define B_STG 16384
#define STG_BYTES (A_STG + B_STG)       // 32768
#define SMEM_BYTES (STAGES * STG_BYTES) // 98304
#define EPI_PITCH_B 272

__global__ __launch_bounds__(256, 2) void gemm_kernel() {
    extern __shared__ char smem[];
    const uint32_t sb = smem_u32(smem);
    const int tid  = threadIdx.x;
    const int lane = tid & 31;
    const int wid  = tid >> 5;
    const int wm   = wid & 1;
    const int wn   = wid >> 1;

    const int n0 = blockIdx.x * 128;
    const int m0 = blockIdx.y * 128;
    const __half* Ag = g_A + (size_t)m0 * Kd;
    const __half* Bg = g_B + (size_t)n0 * Kd;

    float acc[4][4][4];
#pragma unroll
    for (int i = 0; i < 4; i++)
#pragma unroll
        for (int j = 0; j < 4; j++)
#pragma unroll
            for (int c = 0; c < 4; c++) acc[i][j][c] = 0.0f;

    auto load_stage = [&](int stage, int kit) {
        const int k0 = kit * BKc;
        const uint32_t stg = sb + stage * STG_BYTES;
#pragma unroll
        for (int l = 0; l < 8; l++) {
            int cid = l * 256 + tid;
            int isB = cid >> 10;
            int r   = (cid >> 3) & 127;
            int c   = cid & 7;
            const __half* src = (isB ? Bg : Ag) + (size_t)r * Kd + k0 + c * 8;
            cpasync16(stg + isB * A_STG + r * 128 + ((c ^ (r & 7)) << 4), src);
        }
        cp_commit();
    };

    load_stage(0, 0);
    load_stage(1, 1);

    const int a_row_lane = lane & 15;
    const int a_chunk_hi = lane >> 4;

    for (int kit = 0; kit < NK; kit++) {
        const int stage = kit % STAGES;
        if (kit == NK - 1) cp_wait<0>(); else cp_wait<1>();
        __syncthreads();

        if (kit + 2 < NK) load_stage((kit + 2) % STAGES, kit + 2);

        const uint32_t abase = sb + stage * STG_BYTES;
        const uint32_t bbase = abase + A_STG;

#pragma unroll
        for (int kk = 0; kk < 4; kk++) {                 // 4 x K=16
            uint32_t a[4][4], b[4][2];
            const int c = kk * 2 + a_chunk_hi;
#pragma unroll
            for (int i = 0; i < 4; i++) {
                int row = wm * 64 + i * 16 + a_row_lane;
                ldsm_x4(a[i][0], a[i][1], a[i][2], a[i][3],
                        abase + row * 128 + ((c ^ (row & 7)) << 4));
            }
            // B: two ldsm_x4 cover 32 rows x both k-chunks (was 4x ldsm_x2)
#pragma unroll
            for (int j2 = 0; j2 < 2; j2++) {
                int row = wn * 32 + j2 * 16 + a_row_lane;
                ldsm_x4(b[j2 * 2][0], b[j2 * 2 + 1][0],
                        b[j2 * 2][1], b[j2 * 2 + 1][1],
                        bbase + row * 128 + ((c ^ (row & 7)) << 4));
            }
#pragma unroll
            for (int i = 0; i < 4; i++)
#pragma unroll
                for (int j = 0; j < 4; j++)
                    mma16816(acc[i][j][0], acc[i][j][1], acc[i][j][2], acc[i][j][3],
                             a[i][0], a[i][1], a[i][2], a[i][3], b[j][0], b[j][1]);
        }
    }

    // ---- epilogue: f32 frags -> half2 smem staging -> coalesced 16B stores ----
    __syncthreads();
    const int qr = lane >> 2;
    const int qc = lane & 3;
#pragma unroll
    for (int i = 0; i < 4; i++) {
#pragma unroll
        for (int j = 0; j < 4; j++) {
            int r0 = wm * 64 + i * 16 + qr;
            int cb = (wn * 32 + j * 8 + qc * 2) * 2;
            __half2 h2a = __floats2half2_rn(acc[i][j][0], acc[i][j][1]);
            __half2 h2b = __floats2half2_rn(acc[i][j][2], acc[i][j][3]);
            *(__half2*)(smem + r0 * EPI_PITCH_B + cb)       = h2a;
            *(__half2*)(smem + (r0 + 8) * EPI_PITCH_B + cb) = h2b;
        }
    }
    __syncthreads();

#pragma unroll
    for (int l = 0; l < 8; l++) {
        int idx = l * 256 + tid;          // 2048 uint4 (128 rows x 256B)
        int row = idx >> 4;
        int c16 = idx & 15;
        uint4 v = *(uint4*)(smem + row * EPI_PITCH_B + c16 * 16);
        *(uint4*)(g_P + (size_t)(m0 + row) * Nc + n0 + c16 * 8) = v;
    }
}

// ---------------- scan: 1 channel per thread, full grid ----------------
__device__ __forceinline__ float fast_tanh(float a) {
    float e = __expf(2.0f * a);
    return 1.0f - __fdividef(2.0f, e + 1.0f);
}
__device__ __forceinline__ float sigm(float a) {
    return __fdividef(1.0f, 1.0f + __expf(-a));
}

__global__ __launch_bounds__(256) void scan_kernel(
    const float* __restrict__ mz, const float* __restrict__ mr,
    const float* __restrict__ br, const float* __restrict__ bz,
    float* __restrict__ out)
{
    const int idx = blockIdx.x * blockDim.x + threadIdx.x;  // B*H = 65536
    const int b = idx >> 10;
    const int n = idx & 1023;

    const float vmz = mz[n], vmr = mr[n], vbr = br[n], vbz = bz[n];

    const __half* pz = g_P + (size_t)b * Tsz * Nc + n;          // z
    const __half* pr = pz + Hsz;                                 // r
    const __half* ph = pz + 2 * Hsz;                             // h

    const int PF = 8;
    __half az[PF], ar[PF], ah[PF];
#pragma unroll
    for (int p = 0; p < PF; p++) {
        az[p] = __ldcs(pz + (size_t)p * Nc);
        ar[p] = __ldcs(pr + (size_t)p * Nc);
        ah[p] = __ldcs(ph + (size_t)p * Nc);
    }

    float h = 0.0f;
    float* op = out + (size_t)b * Tsz * Hsz + n;
    size_t off = 0;
    for (int t0 = 0; t0 < Tsz; t0 += PF) {
#pragma unroll
        for (int p = 0; p < PF; p++) {
            const float vz = __half2float(az[p]);
            const float vr = __half2float(ar[p]);
            const float vh = __half2float(ah[p]);
            if (t0 + p + PF < Tsz) {
                size_t no = off + (size_t)PF * Nc;
                az[p] = __ldcs(pz + no);
                ar[p] = __ldcs(pr + no);
                ah[p] = __ldcs(ph + no);
            }
            const float r    = fast_tanh(fmaf(h, vmr, vr) + vbr) + 1.0f;
            const float z    = sigm(fmaf(h, vmz, vz) + vbz);
            const float cand = fast_tanh(fmaf(r, h, vh));
            h = fmaf(z, h - cand, cand);
            __stcs(op, h);
            op += Hsz;
            off += Nc;
        }
    }
}

// ---------------- launch (sequential, single stream) ----------------
extern "C" void kernel_launch(void* const* d_in, const int* in_sizes, int n_in,
                              void* d_out, int out_size)
{
    const float* x  = (const float*)d_in[0];
    const float* kz = (const float*)d_in[1];
    const float* kr = (const float*)d_in[2];
    const float* kh = (const float*)d_in[3];
    const float* mz = (const float*)d_in[4];
    const float* mr = (const float*)d_in[5];
    const float* br = (const float*)d_in[6];
    const float* bz = (const float*)d_in[7];
    float* out = (float*)d_out;

    cudaFuncSetAttribute(gemm_kernel, cudaFuncAttributeMaxDynamicSharedMemorySize,
                         SMEM_BYTES);

    convA_kernel<<<(Msz * 128) / 256, 256>>>(x);
    convB_kernel<<<(3 * Hsz * 64) / 256, 256>>>(kz, kr, kh);

    gemm_kernel<<<dim3(Nc / 128, Msz / 128), 256, SMEM_BYTES>>>();

    scan_kernel<<<(Bsz * Hsz) / 256, 256>>>(mz, mr, br, bz, out);
}

// round 13
// speedup vs baseline: 1.6287x; 1.6287x over previous
#include <cuda_runtime.h>
#include <cuda_fp16.h>
#include <math.h>
#include <stdint.h>

// Shapes (fixed): x[64,512,512] f32, k*[512,1024] f32, out[64,512,1024] f32
#define Bsz 64
#define Tsz 512
#define Dsz 512
#define Hsz 1024
#define Msz (Bsz * Tsz)   // 32768
#define Kd  512
#define Nc  3072          // fused N = 3*H, columns interleaved per channel pair

// ---------------- device scratch (static, no runtime alloc) ----------------
// g_P[m][col]: col = (n>>1)*6 + (n&1)*3 + p  -> row layout [z0 r0 h0 z1 r1 h1 | ...]
__device__ __align__(16) __half g_P[(size_t)Msz * Nc];        // 192 MB
__device__ __align__(16) __half g_A[(size_t)Msz * Kd];        // 32 MB
__device__ __align__(16) __half g_B[(size_t)Nc * Kd];         // 3 MB

// ---------------- PTX helpers (base-sm_103 features only) ----------------
__device__ __forceinline__ uint32_t smem_u32(const void* p) {
    uint32_t a;
    asm("{ .reg .u64 t; cvta.to.shared.u64 t, %1; cvt.u32.u64 %0, t; }" : "=r"(a) : "l"(p));
    return a;
}
__device__ __forceinline__ void cpasync16(uint32_t dst, const void* src) {
    asm volatile("cp.async.cg.shared.global [%0], [%1], 16;" :: "r"(dst), "l"(src) : "memory");
}
__device__ __forceinline__ void cp_commit() {
    asm volatile("cp.async.commit_group;" ::: "memory");
}
template <int N>
__device__ __forceinline__ void cp_wait() {
    asm volatile("cp.async.wait_group %0;" :: "n"(N) : "memory");
}
__device__ __forceinline__ void ldsm_x4(uint32_t& d0, uint32_t& d1, uint32_t& d2,
                                        uint32_t& d3, uint32_t addr) {
    asm volatile("ldmatrix.sync.aligned.m8n8.x4.shared.b16 {%0,%1,%2,%3}, [%4];"
                 : "=r"(d0), "=r"(d1), "=r"(d2), "=r"(d3) : "r"(addr));
}
__device__ __forceinline__ void ldsm_x2(uint32_t& d0, uint32_t& d1, uint32_t addr) {
    asm volatile("ldmatrix.sync.aligned.m8n8.x2.shared.b16 {%0,%1}, [%2];"
                 : "=r"(d0), "=r"(d1) : "r"(addr));
}
__device__ __forceinline__ void mma16816(float& c0, float& c1, float& c2, float& c3,
                                         uint32_t a0, uint32_t a1, uint32_t a2, uint32_t a3,
                                         uint32_t b0, uint32_t b1) {
    asm volatile(
        "mma.sync.aligned.m16n8k16.row.col.f32.f16.f16.f32 "
        "{%0,%1,%2,%3}, {%4,%5,%6,%7}, {%8,%9}, {%0,%1,%2,%3};"
        : "+f"(c0), "+f"(c1), "+f"(c2), "+f"(c3)
        : "r"(a0), "r"(a1), "r"(a2), "r"(a3), "r"(b0), "r"(b1));
}
// single-MUFU tanh (sm_75+)
__device__ __forceinline__ float tanh_fast(float x) {
    float y;
    asm("tanh.approx.f32 %0, %1;" : "=f"(y) : "f"(x));
    return y;
}

// ---------------- conversion kernels ----------------
// A[m][k] = fp16(x[m][k])
__global__ __launch_bounds__(256) void convA_kernel(const float* __restrict__ x) {
    int idx = blockIdx.x * blockDim.x + threadIdx.x;       // Msz*128 threads
    int m  = idx >> 7;
    int kg = (idx & 127) << 2;
    float4 v = *(const float4*)(x + (size_t)m * Dsz + kg);
    __half h[4] = {__float2half(v.x), __float2half(v.y),
                   __float2half(v.z), __float2half(v.w)};
    uint64_t hp;
    memcpy(&hp, h, 8);
    *(uint64_t*)(g_A + (size_t)m * Kd + kg) = hp;
}

// B[col][k] = fp16(W_p[k][n]) with col = (n>>1)*6 + (n&1)*3 + p
__global__ __launch_bounds__(256) void convB_kernel(const float* __restrict__ kz,
                                                    const float* __restrict__ kr,
                                                    const float* __restrict__ kh) {
    int idx = blockIdx.x * blockDim.x + threadIdx.x;       // 3*1024*64 threads
    int proj = idx >> 16;
    int r    = idx & 65535;
    int n  = r >> 6;
    int kg = (r & 63) << 3;
    const float* W = (proj == 0) ? kz : (proj == 1) ? kr : kh;
    const int col = (n >> 1) * 6 + (n & 1) * 3 + proj;

    __half h[8];
#pragma unroll
    for (int j = 0; j < 8; j++)
        h[j] = __float2half(W[(size_t)(kg + j) * Hsz + n]);
    uint4 hp;
    memcpy(&hp, h, 16);
    *(uint4*)(g_B + (size_t)col * Kd + kg) = hp;
}

// ---------------- fused mma.sync GEMM (M=32768, N=3072, K=512) ----------------
// BM=128, BN=128, BK=64. 256 threads = 8 warps (2m x 4n), warp tile 64x32.
// 3-stage cp.async pipeline (96KB), 2 CTAs/SM, fp16 epilogue.  (R10 proven)
#define BKc 64
#define STAGES 3
#define NK (Kd / BKc)                   // 8
#define A_STG 16384
#define B_STG 16384
#define STG_BYTES (A_STG + B_STG)       // 32768
#define SMEM_BYTES (STAGES * STG_BYTES) // 98304
#define EPI_PITCH_B 272

__global__ __launch_bounds__(256, 2) void gemm_kernel() {
    extern __shared__ char smem[];
    const uint32_t sb = smem_u32(smem);
    const int tid  = threadIdx.x;
    const int lane = tid & 31;
    const int wid  = tid >> 5;
    const int wm   = wid & 1;
    const int wn   = wid >> 1;

    const int n0 = blockIdx.x * 128;
    const int m0 = blockIdx.y * 128;
    const __half* Ag = g_A + (size_t)m0 * Kd;
    const __half* Bg = g_B + (size_t)n0 * Kd;

    float acc[4][4][4];
#pragma unroll
    for (int i = 0; i < 4; i++)
#pragma unroll
        for (int j = 0; j < 4; j++)
#pragma unroll
            for (int c = 0; c < 4; c++) acc[i][j][c] = 0.0f;

    auto load_stage = [&](int stage, int kit) {
        const int k0 = kit * BKc;
        const uint32_t stg = sb + stage * STG_BYTES;
#pragma unroll
        for (int l = 0; l < 8; l++) {
            int cid = l * 256 + tid;
            int isB = cid >> 10;
            int r   = (cid >> 3) & 127;
            int c   = cid & 7;
            const __half* src = (isB ? Bg : Ag) + (size_t)r * Kd + k0 + c * 8;
            cpasync16(stg + isB * A_STG + r * 128 + ((c ^ (r & 7)) << 4), src);
        }
        cp_commit();
    };

    load_stage(0, 0);
    load_stage(1, 1);

    const int a_row_lane = lane & 15;
    const int a_chunk_hi = lane >> 4;
    const int b_row_lane = lane & 7;
    const int b_chunk_hi = (lane >> 3) & 1;

    for (int kit = 0; kit < NK; kit++) {
        const int stage = kit % STAGES;
        if (kit == NK - 1) cp_wait<0>(); else cp_wait<1>();
        __syncthreads();

        if (kit + 2 < NK) load_stage((kit + 2) % STAGES, kit + 2);

        const uint32_t abase = sb + stage * STG_BYTES;
        const uint32_t bbase = abase + A_STG;

#pragma unroll
        for (int kk = 0; kk < 4; kk++) {                 // 4 x K=16
            uint32_t a[4][4], b[4][2];
#pragma unroll
            for (int i = 0; i < 4; i++) {
                int row = wm * 64 + i * 16 + a_row_lane;
                int c = kk * 2 + a_chunk_hi;
                ldsm_x4(a[i][0], a[i][1], a[i][2], a[i][3],
                        abase + row * 128 + ((c ^ (row & 7)) << 4));
            }
#pragma unroll
            for (int j = 0; j < 4; j++) {
                int row = wn * 32 + j * 8 + b_row_lane;
                int c = kk * 2 + b_chunk_hi;
                ldsm_x2(b[j][0], b[j][1],
                        bbase + row * 128 + ((c ^ (row & 7)) << 4));
            }
#pragma unroll
            for (int i = 0; i < 4; i++)
#pragma unroll
                for (int j = 0; j < 4; j++)
                    mma16816(acc[i][j][0], acc[i][j][1], acc[i][j][2], acc[i][j][3],
                             a[i][0], a[i][1], a[i][2], a[i][3], b[j][0], b[j][1]);
        }
    }

    // ---- epilogue: f32 frags -> half2 smem staging -> coalesced 16B stores ----
    __syncthreads();
    const int qr = lane >> 2;
    const int qc = lane & 3;
#pragma unroll
    for (int i = 0; i < 4; i++) {
#pragma unroll
        for (int j = 0; j < 4; j++) {
            int r0 = wm * 64 + i * 16 + qr;
            int cb = (wn * 32 + j * 8 + qc * 2) * 2;   // byte col within row
            __half2 h2a = __floats2half2_rn(acc[i][j][0], acc[i][j][1]);
            __half2 h2b = __floats2half2_rn(acc[i][j][2], acc[i][j][3]);
            *(__half2*)(smem + r0 * EPI_PITCH_B + cb)       = h2a;
            *(__half2*)(smem + (r0 + 8) * EPI_PITCH_B + cb) = h2b;
        }
    }
    __syncthreads();

#pragma unroll
    for (int l = 0; l < 8; l++) {
        int idx = l * 256 + tid;          // 2048 uint4 (128 rows x 256B)
        int row = idx >> 4;
        int c16 = idx & 15;
        uint4 v = *(uint4*)(smem + row * EPI_PITCH_B + c16 * 16);
        *(uint4*)(g_P + (size_t)(m0 + row) * Nc + n0 + c16 * 8) = v;
    }
}

// ---------------- scan: 2 packed channels per thread (R10) + MUFU tanh ----------------
// sigma(x) = 0.5 + 0.5*tanh(x/2)  -> 3 MUFU per channel-step instead of 6.

__global__ __launch_bounds__(128) void scan_kernel(
    const float* __restrict__ mz, const float* __restrict__ mr,
    const float* __restrict__ br, const float* __restrict__ bz,
    float* __restrict__ out)
{
    const int idx = blockIdx.x * blockDim.x + threadIdx.x;  // B*H/2 = 32768
    const int b  = idx >> 9;          // batch
    const int jj = idx & 511;         // channel pair
    const int i0 = jj * 2;

    const float vmz0 = mz[i0], vmz1 = mz[i0 + 1];
    const float vmr0 = mr[i0], vmr1 = mr[i0 + 1];
    const float vbr0 = br[i0], vbr1 = br[i0 + 1];
    const float vbz0 = bz[i0], vbz1 = bz[i0 + 1];

    // packed projections: 3 uints = 12B = [z0 r0][h0 z1][r1 h1] per t
    const uint32_t* src = (const uint32_t*)(g_P + (size_t)b * Tsz * Nc + jj * 6);
    const int STRIDE_U = Nc / 2;      // uints per timestep (1536)

    const int PF = 8;
    uint32_t u0[PF], u1[PF], u2[PF];
#pragma unroll
    for (int p = 0; p < PF; p++) {
        const uint32_t* s = src + (size_t)p * STRIDE_U;
        u0[p] = __ldcs(s); u1[p] = __ldcs(s + 1); u2[p] = __ldcs(s + 2);
    }

    float h0 = 0.0f, h1 = 0.0f;
    float* op = out + (size_t)b * Tsz * Hsz + i0;
    const uint32_t* sp = src;

    for (int t0 = 0; t0 < Tsz; t0 += PF) {
#pragma unroll
        for (int p = 0; p < PF; p++) {
            float2 a0 = __half22float2(*(__half2*)&u0[p]);  // z0 r0
            float2 a1 = __half22float2(*(__half2*)&u1[p]);  // h0 z1
            float2 a2 = __half22float2(*(__half2*)&u2[p]);  // r1 h1
            if (t0 + p + PF < Tsz) {
                const uint32_t* s = sp + (size_t)(p + PF) * STRIDE_U;
                u0[p] = __ldcs(s); u1[p] = __ldcs(s + 1); u2[p] = __ldcs(s + 2);
            }
            // channel 0
            {
                const float r    = tanh_fast(fmaf(h0, vmr0, a0.y) + vbr0) + 1.0f;
                const float z    = fmaf(0.5f, tanh_fast(0.5f * (fmaf(h0, vmz0, a0.x) + vbz0)), 0.5f);
                const float cand = tanh_fast(fmaf(r, h0, a1.x));
                h0 = fmaf(z, h0 - cand, cand);
            }
            // channel 1
            {
                const float r    = tanh_fast(fmaf(h1, vmr1, a2.x) + vbr1) + 1.0f;
                const float z    = fmaf(0.5f, tanh_fast(0.5f * (fmaf(h1, vmz1, a1.y) + vbz1)), 0.5f);
                const float cand = tanh_fast(fmaf(r, h1, a2.y));
                h1 = fmaf(z, h1 - cand, cand);
            }
            __stcs((float2*)op, make_float2(h0, h1));
            op += Hsz;
        }
        sp += (size_t)PF * STRIDE_U;
    }
}

// ---------------- launch (sequential, single stream — R10) ----------------
extern "C" void kernel_launch(void* const* d_in, const int* in_sizes, int n_in,
                              void* d_out, int out_size)
{
    const float* x  = (const float*)d_in[0];
    const float* kz = (const float*)d_in[1];
    const float* kr = (const float*)d_in[2];
    const float* kh = (const float*)d_in[3];
    const float* mz = (const float*)d_in[4];
    const float* mr = (const float*)d_in[5];
    const float* br = (const float*)d_in[6];
    const float* bz = (const float*)d_in[7];
    float* out = (float*)d_out;

    cudaFuncSetAttribute(gemm_kernel, cudaFuncAttributeMaxDynamicSharedMemorySize,
                         SMEM_BYTES);

    convA_kernel<<<(Msz * 128) / 256, 256>>>(x);
    convB_kernel<<<(3 * Hsz * 64) / 256, 256>>>(kz, kr, kh);

    gemm_kernel<<<dim3(Nc / 128, Msz / 128), 256, SMEM_BYTES>>>();

    scan_kernel<<<(Bsz * Hsz / 2) / 128, 128>>>(mz, mr, br, bz, out);
}